// round 6
// baseline (speedup 1.0000x reference)
#include <cuda_runtime.h>

#define NSEG 256
#define D 128
#define OUT_ELEMS (NSEG * D)

// Scratch (alloc-free rule: __device__ globals).
__device__ int g_counts[NSEG];
__device__ unsigned int g_done;

// ---------------------------------------------------------------------------
// Pass 0: zero output sums, counts, and the completion ticket.
// ---------------------------------------------------------------------------
__global__ void zero_kernel(float* __restrict__ out) {
    int i = blockIdx.x * blockDim.x + threadIdx.x;
    if (i < OUT_ELEMS) out[i] = 0.0f;
    if (i < NSEG) g_counts[i] = 0;
    if (i == 0) g_done = 0;
}

// ---------------------------------------------------------------------------
// Pass 1: segmented sum + fused finalize (last CTA divides by counts).
// One warp owns a contiguous row chunk; lane l holds float4 columns [4l,4l+4).
// Sorted ids: if the chunk's first and last ids match, the WHOLE chunk is one
// segment -> pure streaming loop with no id loads/compares (~97% of warps).
// ---------------------------------------------------------------------------
__device__ __forceinline__ void flush_acc(float* __restrict__ out, int seg_id,
                                          int lane, const float4& acc, int cnt) {
    float* p = out + seg_id * D + lane * 4;
    atomicAdd(p + 0, acc.x);
    atomicAdd(p + 1, acc.y);
    atomicAdd(p + 2, acc.z);
    atomicAdd(p + 3, acc.w);
    if (lane == 0) atomicAdd(&g_counts[seg_id], cnt);
}

__global__ __launch_bounds__(256, 8) void segsum_kernel(
    const float4* __restrict__ inp,   // (n, 32) float4 view of (n, 128) float
    const int* __restrict__ seg,      // (n,) sorted segment ids
    float* __restrict__ out,          // (256, 128) sums -> means
    int n, int nblocks)
{
    const int lane = threadIdx.x & 31;
    const int warp_global = (blockIdx.x * blockDim.x + threadIdx.x) >> 5;
    const int num_warps = (nblocks * (int)blockDim.x) >> 5;

    const int rows_per_warp = (n + num_warps - 1) / num_warps;
    int r = warp_global * rows_per_warp;
    const int r1 = min(n, r + rows_per_warp);

    if (r < r1) {
        const int first = seg[r];
        const int last = seg[r1 - 1];

        if (first == last) {
            // -------- Uniform chunk (common case): pure streaming sum. ------
            float4 acc = make_float4(0.0f, 0.0f, 0.0f, 0.0f);
            const float4* p = inp + (size_t)r * 32 + lane;
            int rows = r1 - r;
            while (rows >= 4) {
                float4 v0 = p[0 * 32];
                float4 v1 = p[1 * 32];
                float4 v2 = p[2 * 32];
                float4 v3 = p[3 * 32];
                acc.x += (v0.x + v1.x) + (v2.x + v3.x);
                acc.y += (v0.y + v1.y) + (v2.y + v3.y);
                acc.z += (v0.z + v1.z) + (v2.z + v3.z);
                acc.w += (v0.w + v1.w) + (v2.w + v3.w);
                p += 4 * 32;
                rows -= 4;
            }
            while (rows > 0) {
                float4 v = *p;
                acc.x += v.x; acc.y += v.y; acc.z += v.z; acc.w += v.w;
                p += 32;
                rows--;
            }
            flush_acc(out, first, lane, acc, r1 - r);
        } else {
            // -------- Boundary chunk (rare): per-row scan. ------------------
            float4 acc = make_float4(0.0f, 0.0f, 0.0f, 0.0f);
            int cnt = 0;
            int cur = first;
            for (; r < r1; ++r) {
                int s = seg[r];
                float4 v = inp[(size_t)r * 32 + lane];
                if (s != cur) {
                    flush_acc(out, cur, lane, acc, cnt);
                    acc = make_float4(0.0f, 0.0f, 0.0f, 0.0f);
                    cnt = 0;
                    cur = s;
                }
                acc.x += v.x; acc.y += v.y; acc.z += v.z; acc.w += v.w;
                cnt++;
            }
            flush_acc(out, cur, lane, acc, cnt);
        }
    }

    // ---- Fused finalize: last CTA to finish divides sums by counts. ----
    __shared__ unsigned int s_is_last;
    __threadfence();             // release our atomics before taking a ticket
    __syncthreads();             // all warps of this CTA have flushed
    if (threadIdx.x == 0) {
        unsigned int ticket = atomicAdd(&g_done, 1u);
        s_is_last = (ticket == (unsigned int)(nblocks - 1)) ? 1u : 0u;
    }
    __syncthreads();
    if (s_is_last) {
        // All other CTAs' atomics are globally visible (fence-before-ticket).
        float4* o4 = (float4*)out;
        for (int j = threadIdx.x; j < OUT_ELEMS / 4; j += blockDim.x) {
            int s = j >> 5;                    // float4 index -> segment (32 f4/row)
            int c = g_counts[s];
            float inv = 1.0f / (float)(c < 1 ? 1 : c);
            float4 v = o4[j];
            v.x *= inv; v.y *= inv; v.z *= inv; v.w *= inv;
            o4[j] = v;
        }
    }
}

// ---------------------------------------------------------------------------
// Launch. d_in[0] = inp (float32, n*128), d_in[1] = batch_seg (int32, n).
// Output: (256, 128) float32 means.
// ---------------------------------------------------------------------------
extern "C" void kernel_launch(void* const* d_in, const int* in_sizes, int n_in,
                              void* d_out, int out_size) {
    const float* inp = (const float*)d_in[0];
    const int* seg = (const int*)d_in[1];
    float* out = (float*)d_out;
    const int n = in_sizes[1];  // number of rows

    zero_kernel<<<(OUT_ELEMS + 255) / 256, 256>>>(out);

    const int blocks = 148 * 8;  // one full wave at occupancy 8
    segsum_kernel<<<blocks, 256>>>((const float4*)inp, seg, out, n, blocks);
}

// round 9
// speedup vs baseline: 1.3720x; 1.3720x over previous
#include <cuda_runtime.h>

#define NSEG 256
#define D 128
#define OUT_ELEMS (NSEG * D)

// Scratch (alloc-free rule: __device__ globals).
__device__ int g_counts[NSEG];

// ---------------------------------------------------------------------------
// Pass 0: zero output sums and counts (d_out is poisoned by the harness).
// ---------------------------------------------------------------------------
__global__ void zero_kernel(float* __restrict__ out) {
    int i = blockIdx.x * blockDim.x + threadIdx.x;
    if (i < OUT_ELEMS) out[i] = 0.0f;
    if (i < NSEG) g_counts[i] = 0;
}

// ---------------------------------------------------------------------------
// Pass 1: segmented sum. One warp owns a contiguous row chunk; lane l holds
// float4 columns [4l, 4l+4). Sorted ids: if the chunk's first and last ids
// match, the whole chunk is one segment -> streaming quad loop with no id
// loads/compares (~97% of warps). No fences here — finalize is a separate
// kernel (fused-threadfence variants measured SLOWER: R4 109us, R5 127us).
// ---------------------------------------------------------------------------
__device__ __forceinline__ void flush_acc(float* __restrict__ out, int seg_id,
                                          int lane, const float4& acc, int cnt) {
    float* p = out + seg_id * D + lane * 4;
    atomicAdd(p + 0, acc.x);
    atomicAdd(p + 1, acc.y);
    atomicAdd(p + 2, acc.z);
    atomicAdd(p + 3, acc.w);
    if (lane == 0) atomicAdd(&g_counts[seg_id], cnt);
}

__global__ __launch_bounds__(256, 8) void segsum_kernel(
    const float4* __restrict__ inp,   // (n, 32) float4 view of (n, 128) float
    const int* __restrict__ seg,      // (n,) sorted segment ids
    float* __restrict__ out,          // (256, 128) sums
    int n)
{
    const int lane = threadIdx.x & 31;
    const int warp_global = (blockIdx.x * blockDim.x + threadIdx.x) >> 5;
    const int num_warps = (gridDim.x * blockDim.x) >> 5;

    const int rows_per_warp = (n + num_warps - 1) / num_warps;
    const int r0 = warp_global * rows_per_warp;
    const int r1 = min(n, r0 + rows_per_warp);
    if (r0 >= r1) return;
    int r = r0;

    const int first = seg[r0];
    const int last = seg[r1 - 1];

    float4 acc = make_float4(0.0f, 0.0f, 0.0f, 0.0f);

    if (first == last) {
        // -------- Uniform chunk (common case): streaming quad loop, indexed
        // addressing (same codegen shape as the proven R3 loop body). --------
        while (r + 4 <= r1) {
            float4 v0 = inp[(size_t)(r + 0) * 32 + lane];
            float4 v1 = inp[(size_t)(r + 1) * 32 + lane];
            float4 v2 = inp[(size_t)(r + 2) * 32 + lane];
            float4 v3 = inp[(size_t)(r + 3) * 32 + lane];
            acc.x += (v0.x + v1.x) + (v2.x + v3.x);
            acc.y += (v0.y + v1.y) + (v2.y + v3.y);
            acc.z += (v0.z + v1.z) + (v2.z + v3.z);
            acc.w += (v0.w + v1.w) + (v2.w + v3.w);
            r += 4;
        }
        for (; r < r1; ++r) {
            float4 v = inp[(size_t)r * 32 + lane];
            acc.x += v.x; acc.y += v.y; acc.z += v.z; acc.w += v.w;
        }
        flush_acc(out, first, lane, acc, r1 - r0);
    } else {
        // -------- Boundary chunk (rare, ~3% of warps): R3's full loop. ------
        int cnt = 0;
        int cur = first;
        while (r + 4 <= r1) {
            int s0 = seg[r];
            int s3 = seg[r + 3];
            float4 v0 = inp[(size_t)(r + 0) * 32 + lane];
            float4 v1 = inp[(size_t)(r + 1) * 32 + lane];
            float4 v2 = inp[(size_t)(r + 2) * 32 + lane];
            float4 v3 = inp[(size_t)(r + 3) * 32 + lane];
            if (s0 == cur && s3 == cur) {
                acc.x += (v0.x + v1.x) + (v2.x + v3.x);
                acc.y += (v0.y + v1.y) + (v2.y + v3.y);
                acc.z += (v0.z + v1.z) + (v2.z + v3.z);
                acc.w += (v0.w + v1.w) + (v2.w + v3.w);
                cnt += 4;
            } else {
                int s1 = seg[r + 1];
                int s2 = seg[r + 2];
                int   ss[4] = {s0, s1, s2, s3};
                float4 vv[4] = {v0, v1, v2, v3};
                #pragma unroll
                for (int i = 0; i < 4; ++i) {
                    if (ss[i] != cur) {
                        flush_acc(out, cur, lane, acc, cnt);
                        acc = make_float4(0.0f, 0.0f, 0.0f, 0.0f);
                        cnt = 0;
                        cur = ss[i];
                    }
                    acc.x += vv[i].x; acc.y += vv[i].y;
                    acc.z += vv[i].z; acc.w += vv[i].w;
                    cnt++;
                }
            }
            r += 4;
        }
        for (; r < r1; ++r) {
            int s = seg[r];
            float4 v = inp[(size_t)r * 32 + lane];
            if (s != cur) {
                flush_acc(out, cur, lane, acc, cnt);
                acc = make_float4(0.0f, 0.0f, 0.0f, 0.0f);
                cnt = 0;
                cur = s;
            }
            acc.x += v.x; acc.y += v.y; acc.z += v.z; acc.w += v.w;
            cnt++;
        }
        flush_acc(out, cur, lane, acc, cnt);
    }
}

// ---------------------------------------------------------------------------
// Pass 2: divide sums by counts (mean).
// ---------------------------------------------------------------------------
__global__ void finalize_kernel(float* __restrict__ out) {
    int i = blockIdx.x * blockDim.x + threadIdx.x;
    if (i >= OUT_ELEMS) return;
    int s = i >> 7;  // / D
    int c = g_counts[s];
    if (c < 1) c = 1;
    out[i] = out[i] / (float)c;
}

// ---------------------------------------------------------------------------
// Launch. d_in[0] = inp (float32, n*128), d_in[1] = batch_seg (int32, n).
// Output: (256, 128) float32 means.
// ---------------------------------------------------------------------------
extern "C" void kernel_launch(void* const* d_in, const int* in_sizes, int n_in,
                              void* d_out, int out_size) {
    const float* inp = (const float*)d_in[0];
    const int* seg = (const int*)d_in[1];
    float* out = (float*)d_out;
    const int n = in_sizes[1];  // number of rows

    zero_kernel<<<(OUT_ELEMS + 255) / 256, 256>>>(out);

    const int blocks = 148 * 8;  // one full wave at occupancy 8
    segsum_kernel<<<blocks, 256>>>((const float4*)inp, seg, out, n);

    finalize_kernel<<<(OUT_ELEMS + 255) / 256, 256>>>(out);
}